// round 1
// baseline (speedup 1.0000x reference)
#include <cuda_runtime.h>
#include <math.h>

// Problem shape (fixed by the dataset)
#define TOK 8192          // B*S tokens
#define HDIM 1024         // hidden
#define NEXP 8            // experts
#define IDIM 4096         // intermediate
#define NASSIGN (TOK*2)   // top-2 assignments

// ---------------- device scratch (no allocations allowed) ----------------
__device__ int   g_counts[NEXP];
__device__ int   g_cursor[NEXP];
__device__ int   g_offset[NEXP];
__device__ int   g_rows[NASSIGN];    // token index per packed slot
__device__ int   g_dest[NASSIGN];    // 2*t + k   (rank within token)
__device__ float g_wgt[NASSIGN];     // routing weight per slot
__device__ int   g_tope[NASSIGN];    // per token: 2 expert ids
__device__ float g_topw[NASSIGN];    // per token: 2 weights
__device__ float g_hbuf[(size_t)NASSIGN * IDIM];  // 268 MB
__device__ float g_ybuf[(size_t)NASSIGN * HDIM];  // 67 MB

// ---------------- init ----------------
__global__ void init_kernel() {
    int i = threadIdx.x;
    if (i < NEXP) { g_counts[i] = 0; g_cursor[i] = 0; }
}

// ---------------- gating: one warp per token ----------------
__global__ void gate_kernel(const float* __restrict__ x,
                            const float* __restrict__ gw) {
    int warp = (blockIdx.x * blockDim.x + threadIdx.x) >> 5;
    int lane = threadIdx.x & 31;
    if (warp >= TOK) return;
    const float* xr = x + (size_t)warp * HDIM;
    float acc[NEXP];
#pragma unroll
    for (int e = 0; e < NEXP; e++) acc[e] = 0.f;
    for (int h = lane; h < HDIM; h += 32) {
        float xv = xr[h];
        const float* g = gw + (size_t)h * NEXP;
#pragma unroll
        for (int e = 0; e < NEXP; e++) acc[e] = fmaf(xv, g[e], acc[e]);
    }
#pragma unroll
    for (int e = 0; e < NEXP; e++) {
#pragma unroll
        for (int off = 16; off > 0; off >>= 1)
            acc[e] += __shfl_xor_sync(0xffffffffu, acc[e], off);
    }
    if (lane == 0) {
        int e0 = 0; float v0 = acc[0];
#pragma unroll
        for (int e = 1; e < NEXP; e++) if (acc[e] > v0) { v0 = acc[e]; e0 = e; }
        int e1 = -1; float v1 = -1e30f;
#pragma unroll
        for (int e = 0; e < NEXP; e++)
            if (e != e0 && acc[e] > v1) { v1 = acc[e]; e1 = e; }
        // renormalized top-2 softmax weights: exp cancels the full denominator
        float p1 = expf(v1 - v0);
        float s  = 1.f + p1;
        float w0 = 1.f / s;
        float w1 = p1 / s;
        int t = warp;
        g_tope[2*t]   = e0;  g_topw[2*t]   = w0;
        g_tope[2*t+1] = e1;  g_topw[2*t+1] = w1;
        atomicAdd(&g_counts[e0], 1);
        atomicAdd(&g_counts[e1], 1);
    }
}

// ---------------- exclusive scan over 8 counts ----------------
__global__ void scan_kernel() {
    int s = 0;
    for (int e = 0; e < NEXP; e++) {
        g_offset[e] = s;
        s += g_counts[e];
        g_cursor[e] = 0;
    }
}

// ---------------- compaction ----------------
__global__ void fill_kernel() {
    int t = blockIdx.x * blockDim.x + threadIdx.x;
    if (t >= TOK) return;
#pragma unroll
    for (int k = 0; k < 2; k++) {
        int e = g_tope[2*t + k];
        int slot = g_offset[e] + atomicAdd(&g_cursor[e], 1);
        g_rows[slot] = t;
        g_dest[slot] = 2*t + k;
        g_wgt[slot]  = g_topw[2*t + k];
    }
}

// ---------------- GEMM1: h = silu(X@w1) * (X@w3), gathered rows ----------
// tile: BM=128, BN=64, BK=16, 256 threads, 8x4 per thread, dual accumulators
__global__ __launch_bounds__(256) void gemm1_kernel(
    const float* __restrict__ x,
    const float* __restrict__ w1,
    const float* __restrict__ w3) {
    int e = blockIdx.z;
    int count = g_counts[e];
    int mbase = blockIdx.y * 128;
    if (mbase >= count) return;
    int off   = g_offset[e];
    int nbase = blockIdx.x * 64;
    const float* B1 = w1 + (size_t)e * HDIM * IDIM;
    const float* B3 = w3 + (size_t)e * HDIM * IDIM;

    __shared__ float As [16][128];
    __shared__ float Bs1[16][64];
    __shared__ float Bs3[16][64];

    int tid  = threadIdx.x;
    int arow = tid >> 1;            // 0..127
    int aq0  = (tid & 1) * 2;       // quad base 0 or 2 (each quad = 4 k's)
    int rclamp = mbase + arow; if (rclamp >= count) rclamp = count - 1;
    const float* arow_ptr = x + (size_t)g_rows[off + rclamp] * HDIM;

    int bk = tid >> 4;              // 0..15 (k within tile)
    int bn = (tid & 15) * 4;        // col quad

    int tm = (tid >> 4) * 8;        // output rows tm..tm+7
    int tn = (tid & 15) * 4;        // output cols tn..tn+3

    float c1[8][4], c3[8][4];
#pragma unroll
    for (int i = 0; i < 8; i++)
#pragma unroll
        for (int j = 0; j < 4; j++) { c1[i][j] = 0.f; c3[i][j] = 0.f; }

    for (int k0 = 0; k0 < HDIM; k0 += 16) {
        float4 a0 = *(const float4*)(arow_ptr + k0 + aq0 * 4);
        float4 a1 = *(const float4*)(arow_ptr + k0 + aq0 * 4 + 4);
        As[aq0*4+0][arow] = a0.x; As[aq0*4+1][arow] = a0.y;
        As[aq0*4+2][arow] = a0.z; As[aq0*4+3][arow] = a0.w;
        As[aq0*4+4][arow] = a1.x; As[aq0*4+5][arow] = a1.y;
        As[aq0*4+6][arow] = a1.z; As[aq0*4+7][arow] = a1.w;
        const float* b1p = B1 + (size_t)(k0 + bk) * IDIM + nbase + bn;
        const float* b3p = B3 + (size_t)(k0 + bk) * IDIM + nbase + bn;
        *(float4*)&Bs1[bk][bn] = *(const float4*)b1p;
        *(float4*)&Bs3[bk][bn] = *(const float4*)b3p;
        __syncthreads();
#pragma unroll
        for (int kk = 0; kk < 16; kk++) {
            float4 av0 = *(const float4*)&As[kk][tm];
            float4 av1 = *(const float4*)&As[kk][tm + 4];
            float a[8] = {av0.x, av0.y, av0.z, av0.w, av1.x, av1.y, av1.z, av1.w};
            float4 bb1 = *(const float4*)&Bs1[kk][tn];
            float4 bb3 = *(const float4*)&Bs3[kk][tn];
            float b1r[4] = {bb1.x, bb1.y, bb1.z, bb1.w};
            float b3r[4] = {bb3.x, bb3.y, bb3.z, bb3.w};
#pragma unroll
            for (int i = 0; i < 8; i++) {
#pragma unroll
                for (int j = 0; j < 4; j++) {
                    c1[i][j] = fmaf(a[i], b1r[j], c1[i][j]);
                    c3[i][j] = fmaf(a[i], b3r[j], c3[i][j]);
                }
            }
        }
        __syncthreads();
    }
#pragma unroll
    for (int i = 0; i < 8; i++) {
        int rr = mbase + tm + i;
        if (rr < count) {
            float* dst = g_hbuf + (size_t)(off + rr) * IDIM + nbase + tn;
            float4 o;
            float z;
            z = c1[i][0]; o.x = (z / (1.f + expf(-z))) * c3[i][0];
            z = c1[i][1]; o.y = (z / (1.f + expf(-z))) * c3[i][1];
            z = c1[i][2]; o.z = (z / (1.f + expf(-z))) * c3[i][2];
            z = c1[i][3]; o.w = (z / (1.f + expf(-z))) * c3[i][3];
            *(float4*)dst = o;
        }
    }
}

// ---------------- GEMM2: y = h @ w2, scaled scatter to ybuf -------------
__global__ __launch_bounds__(256) void gemm2_kernel(const float* __restrict__ w2) {
    int e = blockIdx.z;
    int count = g_counts[e];
    int mbase = blockIdx.y * 128;
    if (mbase >= count) return;
    int off   = g_offset[e];
    int nbase = blockIdx.x * 64;
    const float* B2 = w2 + (size_t)e * IDIM * HDIM;

    __shared__ float As[16][128];
    __shared__ float Bs[16][64];

    int tid  = threadIdx.x;
    int arow = tid >> 1;
    int aq0  = (tid & 1) * 2;
    int rclamp = mbase + arow; if (rclamp >= count) rclamp = count - 1;
    const float* arow_ptr = g_hbuf + (size_t)(off + rclamp) * IDIM;

    int bk = tid >> 4;
    int bn = (tid & 15) * 4;
    int tm = (tid >> 4) * 8;
    int tn = (tid & 15) * 4;

    float c[8][4];
#pragma unroll
    for (int i = 0; i < 8; i++)
#pragma unroll
        for (int j = 0; j < 4; j++) c[i][j] = 0.f;

    for (int k0 = 0; k0 < IDIM; k0 += 16) {
        float4 a0 = *(const float4*)(arow_ptr + k0 + aq0 * 4);
        float4 a1 = *(const float4*)(arow_ptr + k0 + aq0 * 4 + 4);
        As[aq0*4+0][arow] = a0.x; As[aq0*4+1][arow] = a0.y;
        As[aq0*4+2][arow] = a0.z; As[aq0*4+3][arow] = a0.w;
        As[aq0*4+4][arow] = a1.x; As[aq0*4+5][arow] = a1.y;
        As[aq0*4+6][arow] = a1.z; As[aq0*4+7][arow] = a1.w;
        const float* bp = B2 + (size_t)(k0 + bk) * HDIM + nbase + bn;
        *(float4*)&Bs[bk][bn] = *(const float4*)bp;
        __syncthreads();
#pragma unroll
        for (int kk = 0; kk < 16; kk++) {
            float4 av0 = *(const float4*)&As[kk][tm];
            float4 av1 = *(const float4*)&As[kk][tm + 4];
            float a[8] = {av0.x, av0.y, av0.z, av0.w, av1.x, av1.y, av1.z, av1.w};
            float4 bb = *(const float4*)&Bs[kk][tn];
            float br[4] = {bb.x, bb.y, bb.z, bb.w};
#pragma unroll
            for (int i = 0; i < 8; i++) {
#pragma unroll
                for (int j = 0; j < 4; j++)
                    c[i][j] = fmaf(a[i], br[j], c[i][j]);
            }
        }
        __syncthreads();
    }
#pragma unroll
    for (int i = 0; i < 8; i++) {
        int rr = mbase + tm + i;
        if (rr < count) {
            int slot = off + rr;
            float w = g_wgt[slot];
            int   d = g_dest[slot];
            float4 o = { w * c[i][0], w * c[i][1], w * c[i][2], w * c[i][3] };
            *(float4*)(g_ybuf + (size_t)d * HDIM + nbase + tn) = o;
        }
    }
}

// ---------------- combine: out[t] = y[2t] + y[2t+1] ----------------
__global__ void combine_kernel(float* __restrict__ out) {
    const int W = HDIM / 4;
    int i = blockIdx.x * blockDim.x + threadIdx.x;   // float4 index
    if (i >= TOK * W) return;
    int t = i / W, col = i % W;
    const float4* y = (const float4*)g_ybuf;
    float4 a = y[(size_t)(2 * t) * W + col];
    float4 b = y[(size_t)(2 * t + 1) * W + col];
    float4 o = { a.x + b.x, a.y + b.y, a.z + b.z, a.w + b.w };
    ((float4*)out)[i] = o;
}

// ---------------- launch ----------------
extern "C" void kernel_launch(void* const* d_in, const int* in_sizes, int n_in,
                              void* d_out, int out_size) {
    const float* x  = (const float*)d_in[0];   // [T, H]
    const float* gw = (const float*)d_in[1];   // [H, E]
    const float* w1 = (const float*)d_in[2];   // [E, H, I]
    const float* w3 = (const float*)d_in[3];   // [E, H, I]
    const float* w2 = (const float*)d_in[4];   // [E, I, H]
    float* out = (float*)d_out;                // [T, H]

    init_kernel<<<1, 32>>>();
    gate_kernel<<<TOK / 8, 256>>>(x, gw);      // 8 warps per block
    scan_kernel<<<1, 1>>>();
    fill_kernel<<<TOK / 256, 256>>>();

    dim3 g1(IDIM / 64, TOK / 128, NEXP);
    gemm1_kernel<<<g1, 256>>>(x, w1, w3);

    dim3 g2(HDIM / 64, TOK / 128, NEXP);
    gemm2_kernel<<<g2, 256>>>(w2);

    combine_kernel<<<(TOK * (HDIM / 4)) / 256, 256>>>(out);
}

// round 7
// speedup vs baseline: 1.0366x; 1.0366x over previous
#include <cuda_runtime.h>
#include <cuda_bf16.h>
#include <stdint.h>
#include <math.h>

// Problem shape (fixed by the dataset)
#define TOK 8192          // B*S tokens
#define HDIM 1024         // hidden
#define NEXP 8            // experts
#define IDIM 4096         // intermediate
#define NASSIGN (TOK*2)   // top-2 assignments

// ---------------- device scratch (no allocations allowed) ----------------
__device__ int   g_counts[NEXP];
__device__ int   g_cursor[NEXP];
__device__ int   g_offset[NEXP];
__device__ int   g_rows[NASSIGN];    // token index per packed slot
__device__ int   g_dest[NASSIGN];    // 2*t + k   (rank within token)
__device__ float g_wgt[NASSIGN];     // routing weight per slot
__device__ int   g_tope[NASSIGN];    // per token: 2 expert ids
__device__ float g_topw[NASSIGN];    // per token: 2 weights
__device__ float g_hbuf[(size_t)NASSIGN * IDIM];  // 268 MB
__device__ float g_ybuf[(size_t)NASSIGN * HDIM];  // 67 MB

// ---------------- packed f32x2 helpers (B300 FFMA2) ----------------
__device__ __forceinline__ unsigned long long pk(float lo, float hi) {
    unsigned long long r;
    asm("mov.b64 %0, {%1, %2};" : "=l"(r) : "f"(lo), "f"(hi));
    return r;
}
__device__ __forceinline__ void upk(unsigned long long v, float& lo, float& hi) {
    asm("mov.b64 {%0, %1}, %2;" : "=f"(lo), "=f"(hi) : "l"(v));
}
__device__ __forceinline__ void fma2(unsigned long long& c,
                                     unsigned long long a,
                                     unsigned long long b) {
    asm("fma.rn.f32x2 %0, %1, %2, %0;" : "+l"(c) : "l"(a), "l"(b));
}

// ---------------- init ----------------
__global__ void init_kernel() {
    int i = threadIdx.x;
    if (i < NEXP) { g_counts[i] = 0; g_cursor[i] = 0; }
}

// ---------------- gating: one warp per token ----------------
__global__ void gate_kernel(const float* __restrict__ x,
                            const float* __restrict__ gw) {
    int warp = (blockIdx.x * blockDim.x + threadIdx.x) >> 5;
    int lane = threadIdx.x & 31;
    if (warp >= TOK) return;
    const float* xr = x + (size_t)warp * HDIM;
    float acc[NEXP];
#pragma unroll
    for (int e = 0; e < NEXP; e++) acc[e] = 0.f;
    for (int h = lane; h < HDIM; h += 32) {
        float xv = xr[h];
        const float* g = gw + (size_t)h * NEXP;
#pragma unroll
        for (int e = 0; e < NEXP; e++) acc[e] = fmaf(xv, g[e], acc[e]);
    }
#pragma unroll
    for (int e = 0; e < NEXP; e++) {
#pragma unroll
        for (int off = 16; off > 0; off >>= 1)
            acc[e] += __shfl_xor_sync(0xffffffffu, acc[e], off);
    }
    if (lane == 0) {
        int e0 = 0; float v0 = acc[0];
#pragma unroll
        for (int e = 1; e < NEXP; e++) if (acc[e] > v0) { v0 = acc[e]; e0 = e; }
        int e1 = -1; float v1 = -1e30f;
#pragma unroll
        for (int e = 0; e < NEXP; e++)
            if (e != e0 && acc[e] > v1) { v1 = acc[e]; e1 = e; }
        float p1 = expf(v1 - v0);
        float s  = 1.f + p1;
        float w0 = 1.f / s;
        float w1 = p1 / s;
        int t = warp;
        g_tope[2*t]   = e0;  g_topw[2*t]   = w0;
        g_tope[2*t+1] = e1;  g_topw[2*t+1] = w1;
        atomicAdd(&g_counts[e0], 1);
        atomicAdd(&g_counts[e1], 1);
    }
}

// ---------------- exclusive scan over 8 counts ----------------
__global__ void scan_kernel() {
    int s = 0;
    for (int e = 0; e < NEXP; e++) {
        g_offset[e] = s;
        s += g_counts[e];
        g_cursor[e] = 0;
    }
}

// ---------------- compaction ----------------
__global__ void fill_kernel() {
    int t = blockIdx.x * blockDim.x + threadIdx.x;
    if (t >= TOK) return;
#pragma unroll
    for (int k = 0; k < 2; k++) {
        int e = g_tope[2*t + k];
        int slot = g_offset[e] + atomicAdd(&g_cursor[e], 1);
        g_rows[slot] = t;
        g_dest[slot] = 2*t + k;
        g_wgt[slot]  = g_topw[2*t + k];
    }
}

// ---------------- GEMM1: h = silu(X@w1) * (X@w3), gathered rows ----------
// tile: BM=128, BN=64, BK=16, 256 threads, 8x4 per thread, dual accumulators
// inner product uses packed fma.rn.f32x2 over M-row pairs
__global__ __launch_bounds__(256) void gemm1_kernel(
    const float* __restrict__ x,
    const float* __restrict__ w1,
    const float* __restrict__ w3) {
    int e = blockIdx.z;
    int count = g_counts[e];
    int mbase = blockIdx.y * 128;
    if (mbase >= count) return;
    int off   = g_offset[e];
    int nbase = blockIdx.x * 64;
    const float* B1 = w1 + (size_t)e * HDIM * IDIM;
    const float* B3 = w3 + (size_t)e * HDIM * IDIM;

    __shared__ float As [16][128];
    __shared__ float Bs1[16][64];
    __shared__ float Bs3[16][64];

    int tid  = threadIdx.x;
    int arow = tid >> 1;            // 0..127
    int aq0  = (tid & 1) * 2;       // quad base 0 or 2 (each quad = 4 k's)
    int rclamp = mbase + arow; if (rclamp >= count) rclamp = count - 1;
    const float* arow_ptr = x + (size_t)g_rows[off + rclamp] * HDIM;

    int bk = tid >> 4;              // 0..15 (k within tile)
    int bn = (tid & 15) * 4;        // col quad

    int tm = (tid >> 4) * 8;        // output rows tm..tm+7
    int tn = (tid & 15) * 4;        // output cols tn..tn+3

    // packed accumulators: c1p[i2][j] = (c1[2*i2][j], c1[2*i2+1][j])
    unsigned long long c1p[4][4], c3p[4][4];
    unsigned long long z64 = pk(0.f, 0.f);
#pragma unroll
    for (int i = 0; i < 4; i++)
#pragma unroll
        for (int j = 0; j < 4; j++) { c1p[i][j] = z64; c3p[i][j] = z64; }

    for (int k0 = 0; k0 < HDIM; k0 += 16) {
        float4 a0 = *(const float4*)(arow_ptr + k0 + aq0 * 4);
        float4 a1 = *(const float4*)(arow_ptr + k0 + aq0 * 4 + 4);
        As[aq0*4+0][arow] = a0.x; As[aq0*4+1][arow] = a0.y;
        As[aq0*4+2][arow] = a0.z; As[aq0*4+3][arow] = a0.w;
        As[aq0*4+4][arow] = a1.x; As[aq0*4+5][arow] = a1.y;
        As[aq0*4+6][arow] = a1.z; As[aq0*4+7][arow] = a1.w;
        const float* b1p = B1 + (size_t)(k0 + bk) * IDIM + nbase + bn;
        const float* b3p = B3 + (size_t)(k0 + bk) * IDIM + nbase + bn;
        *(float4*)&Bs1[bk][bn] = *(const float4*)b1p;
        *(float4*)&Bs3[bk][bn] = *(const float4*)b3p;
        __syncthreads();
#pragma unroll
        for (int kk = 0; kk < 16; kk++) {
            float4 av0 = *(const float4*)&As[kk][tm];
            float4 av1 = *(const float4*)&As[kk][tm + 4];
            unsigned long long ap[4];
            ap[0] = pk(av0.x, av0.y); ap[1] = pk(av0.z, av0.w);
            ap[2] = pk(av1.x, av1.y); ap[3] = pk(av1.z, av1.w);
            float4 bb1 = *(const float4*)&Bs1[kk][tn];
            float4 bb3 = *(const float4*)&Bs3[kk][tn];
            unsigned long long bp1[4], bp3[4];
            bp1[0] = pk(bb1.x, bb1.x); bp1[1] = pk(bb1.y, bb1.y);
            bp1[2] = pk(bb1.z, bb1.z); bp1[3] = pk(bb1.w, bb1.w);
            bp3[0] = pk(bb3.x, bb3.x); bp3[1] = pk(bb3.y, bb3.y);
            bp3[2] = pk(bb3.z, bb3.z); bp3[3] = pk(bb3.w, bb3.w);
#pragma unroll
            for (int i2 = 0; i2 < 4; i2++) {
#pragma unroll
                for (int j = 0; j < 4; j++) {
                    fma2(c1p[i2][j], ap[i2], bp1[j]);
                    fma2(c3p[i2][j], ap[i2], bp3[j]);
                }
            }
        }
        __syncthreads();
    }
#pragma unroll
    for (int i2 = 0; i2 < 4; i2++) {
        float c1lo[4], c1hi[4], c3lo[4], c3hi[4];
#pragma unroll
        for (int j = 0; j < 4; j++) {
            upk(c1p[i2][j], c1lo[j], c1hi[j]);
            upk(c3p[i2][j], c3lo[j], c3hi[j]);
        }
        int r0 = mbase + tm + 2 * i2;
        if (r0 < count) {
            float* dst = g_hbuf + (size_t)(off + r0) * IDIM + nbase + tn;
            float4 o; float z;
            z = c1lo[0]; o.x = (z / (1.f + expf(-z))) * c3lo[0];
            z = c1lo[1]; o.y = (z / (1.f + expf(-z))) * c3lo[1];
            z = c1lo[2]; o.z = (z / (1.f + expf(-z))) * c3lo[2];
            z = c1lo[3]; o.w = (z / (1.f + expf(-z))) * c3lo[3];
            *(float4*)dst = o;
        }
        if (r0 + 1 < count) {
            float* dst = g_hbuf + (size_t)(off + r0 + 1) * IDIM + nbase + tn;
            float4 o; float z;
            z = c1hi[0]; o.x = (z / (1.f + expf(-z))) * c3hi[0];
            z = c1hi[1]; o.y = (z / (1.f + expf(-z))) * c3hi[1];
            z = c1hi[2]; o.z = (z / (1.f + expf(-z))) * c3hi[2];
            z = c1hi[3]; o.w = (z / (1.f + expf(-z))) * c3hi[3];
            *(float4*)dst = o;
        }
    }
}

// ---------------- GEMM2: y = h @ w2, scaled scatter to ybuf -------------
__global__ __launch_bounds__(256) void gemm2_kernel(const float* __restrict__ w2) {
    int e = blockIdx.z;
    int count = g_counts[e];
    int mbase = blockIdx.y * 128;
    if (mbase >= count) return;
    int off   = g_offset[e];
    int nbase = blockIdx.x * 64;
    const float* B2 = w2 + (size_t)e * IDIM * HDIM;

    __shared__ float As[16][128];
    __shared__ float Bs[16][64];

    int tid  = threadIdx.x;
    int arow = tid >> 1;
    int aq0  = (tid & 1) * 2;
    int rclamp = mbase + arow; if (rclamp >= count) rclamp = count - 1;
    const float* arow_ptr = g_hbuf + (size_t)(off + rclamp) * IDIM;

    int bk = tid >> 4;
    int bn = (tid & 15) * 4;
    int tm = (tid >> 4) * 8;
    int tn = (tid & 15) * 4;

    unsigned long long cp[4][4];
    unsigned long long z64 = pk(0.f, 0.f);
#pragma unroll
    for (int i = 0; i < 4; i++)
#pragma unroll
        for (int j = 0; j < 4; j++) cp[i][j] = z64;

    for (int k0 = 0; k0 < IDIM; k0 += 16) {
        float4 a0 = *(const float4*)(arow_ptr + k0 + aq0 * 4);
        float4 a1 = *(const float4*)(arow_ptr + k0 + aq0 * 4 + 4);
        As[aq0*4+0][arow] = a0.x; As[aq0*4+1][arow] = a0.y;
        As[aq0*4+2][arow] = a0.z; As[aq0*4+3][arow] = a0.w;
        As[aq0*4+4][arow] = a1.x; As[aq0*4+5][arow] = a1.y;
        As[aq0*4+6][arow] = a1.z; As[aq0*4+7][arow] = a1.w;
        const float* bp = B2 + (size_t)(k0 + bk) * HDIM + nbase + bn;
        *(float4*)&Bs[bk][bn] = *(const float4*)bp;
        __syncthreads();
#pragma unroll
        for (int kk = 0; kk < 16; kk++) {
            float4 av0 = *(const float4*)&As[kk][tm];
            float4 av1 = *(const float4*)&As[kk][tm + 4];
            unsigned long long ap[4];
            ap[0] = pk(av0.x, av0.y); ap[1] = pk(av0.z, av0.w);
            ap[2] = pk(av1.x, av1.y); ap[3] = pk(av1.z, av1.w);
            float4 bb = *(const float4*)&Bs[kk][tn];
            unsigned long long bp2[4];
            bp2[0] = pk(bb.x, bb.x); bp2[1] = pk(bb.y, bb.y);
            bp2[2] = pk(bb.z, bb.z); bp2[3] = pk(bb.w, bb.w);
#pragma unroll
            for (int i2 = 0; i2 < 4; i2++) {
#pragma unroll
                for (int j = 0; j < 4; j++)
                    fma2(cp[i2][j], ap[i2], bp2[j]);
            }
        }
        __syncthreads();
    }
#pragma unroll
    for (int i2 = 0; i2 < 4; i2++) {
        float clo[4], chi[4];
#pragma unroll
        for (int j = 0; j < 4; j++) upk(cp[i2][j], clo[j], chi[j]);
        int r0 = mbase + tm + 2 * i2;
        if (r0 < count) {
            int slot = off + r0;
            float w = g_wgt[slot];
            int   d = g_dest[slot];
            float4 o = { w * clo[0], w * clo[1], w * clo[2], w * clo[3] };
            *(float4*)(g_ybuf + (size_t)d * HDIM + nbase + tn) = o;
        }
        if (r0 + 1 < count) {
            int slot = off + r0 + 1;
            float w = g_wgt[slot];
            int   d = g_dest[slot];
            float4 o = { w * chi[0], w * chi[1], w * chi[2], w * chi[3] };
            *(float4*)(g_ybuf + (size_t)d * HDIM + nbase + tn) = o;
        }
    }
}

// ---------------- combine: out[t] = y[2t] + y[2t+1] ----------------
__global__ void combine_kernel(float* __restrict__ out) {
    const int W = HDIM / 4;
    int i = blockIdx.x * blockDim.x + threadIdx.x;   // float4 index
    if (i >= TOK * W) return;
    int t = i / W, col = i % W;
    const float4* y = (const float4*)g_ybuf;
    float4 a = y[(size_t)(2 * t) * W + col];
    float4 b = y[(size_t)(2 * t + 1) * W + col];
    float4 o = { a.x + b.x, a.y + b.y, a.z + b.z, a.w + b.w };
    ((float4*)out)[i] = o;
}

// ---------------- launch ----------------
extern "C" void kernel_launch(void* const* d_in, const int* in_sizes, int n_in,
                              void* d_out, int out_size) {
    const float* x  = (const float*)d_in[0];   // [T, H]
    const float* gw = (const float*)d_in[1];   // [H, E]
    const float* w1 = (const float*)d_in[2];   // [E, H, I]
    const float* w3 = (const float*)d_in[3];   // [E, H, I]
    const float* w2 = (const float*)d_in[4];   // [E, I, H]
    float* out = (float*)d_out;                // [T, H]

    init_kernel<<<1, 32>>>();
    gate_kernel<<<TOK / 8, 256>>>(x, gw);      // 8 warps per block
    scan_kernel<<<1, 1>>>();
    fill_kernel<<<TOK / 256, 256>>>();

    dim3 g1(IDIM / 64, TOK / 128, NEXP);
    gemm1_kernel<<<g1, 256>>>(x, w1, w3);

    dim3 g2(HDIM / 64, TOK / 128, NEXP);
    gemm2_kernel<<<g2, 256>>>(w2);

    combine_kernel<<<(TOK * (HDIM / 4)) / 256, 256>>>(out);
}